// round 1
// baseline (speedup 1.0000x reference)
#include <cuda_runtime.h>
#include <math.h>

// ---------------- problem constants ----------------
#define BB 2
#define SS 2048
#define DD 1024
#define HH 16
#define HD 64
#define LL 8
#define VV 32000
#define MM (BB*SS)          // 4096 rows

// ---------------- scratch (device globals; no cudaMalloc allowed) ----------
__device__ float g_x[MM*DD];
__device__ float g_h[MM*DD];
__device__ float g_q[MM*DD];
__device__ float g_k[MM*DD];
__device__ float g_v[MM*DD];
__device__ float g_o[MM*DD];

// ---------------- embedding lookup ----------------
__global__ void embed_kernel(const int* __restrict__ tokens,
                             const float* __restrict__ emb,
                             float* __restrict__ x) {
    int row = blockIdx.x;
    int tok = tokens[row];
    const float4* src = (const float4*)(emb + (size_t)tok * DD);
    float4* dst = (float4*)(x + (size_t)row * DD);
    for (int i = threadIdx.x; i < DD/4; i += blockDim.x) dst[i] = src[i];
}

// ---------------- layernorm (one block per row) ----------------
__global__ void ln_kernel(const float* __restrict__ x,
                          const float* __restrict__ gw,
                          const float* __restrict__ bw,
                          float* __restrict__ out) {
    int row = blockIdx.x;
    const float* xr = x + (size_t)row * DD;
    float s = 0.f, s2 = 0.f;
    for (int i = threadIdx.x; i < DD; i += 256) {
        float v = xr[i];
        s += v;
        s2 = fmaf(v, v, s2);
    }
    __shared__ float rs[8], rs2[8];
    #pragma unroll
    for (int o = 16; o > 0; o >>= 1) {
        s  += __shfl_down_sync(0xffffffffu, s,  o);
        s2 += __shfl_down_sync(0xffffffffu, s2, o);
    }
    int w = threadIdx.x >> 5;
    if ((threadIdx.x & 31) == 0) { rs[w] = s; rs2[w] = s2; }
    __syncthreads();
    __shared__ float mean_s, rstd_s;
    if (threadIdx.x == 0) {
        float ts = 0.f, ts2 = 0.f;
        #pragma unroll
        for (int i = 0; i < 8; i++) { ts += rs[i]; ts2 += rs2[i]; }
        float m = ts / (float)DD;
        float var = ts2 / (float)DD - m * m;
        mean_s = m;
        rstd_s = rsqrtf(var + 1e-5f);
    }
    __syncthreads();
    float m = mean_s, r = rstd_s;
    float* orow = out + (size_t)row * DD;
    for (int i = threadIdx.x; i < DD; i += 256)
        orow[i] = (xr[i] - m) * r * gw[i] + bw[i];
}

// ---------------- generic GEMM: C[M,N] = A[M,K] @ W[N,K]^T (+ R) ----------
// BM=BN=64, BK=16, 256 threads, 4x4 microtile. M,N,K all divisible by tile.
template<bool RESID>
__global__ void gemm_kernel(const float* __restrict__ A,
                            const float* __restrict__ W,
                            const float* __restrict__ R,
                            float* __restrict__ C,
                            int N, int K) {
    __shared__ float As[16 * 66];
    __shared__ float Bs[16 * 66];
    int tid = threadIdx.x;
    int tx = tid & 15, ty = tid >> 4;
    int m0 = blockIdx.y * 64, n0 = blockIdx.x * 64;
    int lm = tid >> 2;            // 0..63
    int lk = (tid & 3) * 4;       // 0,4,8,12

    const float* Aptr = A + (size_t)(m0 + lm) * K + lk;
    const float* Wptr = W + (size_t)(n0 + lm) * K + lk;

    float acc[4][4] = {};
    for (int k0 = 0; k0 < K; k0 += 16) {
        float4 a4 = *(const float4*)(Aptr + k0);
        float4 w4 = *(const float4*)(Wptr + k0);
        As[(lk+0)*66 + lm] = a4.x; As[(lk+1)*66 + lm] = a4.y;
        As[(lk+2)*66 + lm] = a4.z; As[(lk+3)*66 + lm] = a4.w;
        Bs[(lk+0)*66 + lm] = w4.x; Bs[(lk+1)*66 + lm] = w4.y;
        Bs[(lk+2)*66 + lm] = w4.z; Bs[(lk+3)*66 + lm] = w4.w;
        __syncthreads();
        #pragma unroll
        for (int kk = 0; kk < 16; kk++) {
            float ra[4], rb[4];
            #pragma unroll
            for (int i = 0; i < 4; i++) ra[i] = As[kk*66 + ty*4 + i];
            #pragma unroll
            for (int j = 0; j < 4; j++) rb[j] = Bs[kk*66 + tx*4 + j];
            #pragma unroll
            for (int i = 0; i < 4; i++)
                #pragma unroll
                for (int j = 0; j < 4; j++)
                    acc[i][j] = fmaf(ra[i], rb[j], acc[i][j]);
        }
        __syncthreads();
    }
    #pragma unroll
    for (int i = 0; i < 4; i++) {
        size_t idx = (size_t)(m0 + ty*4 + i) * N + n0 + tx*4;
        float4 v = make_float4(acc[i][0], acc[i][1], acc[i][2], acc[i][3]);
        if (RESID) {
            float4 r = *(const float4*)(R + idx);
            v.x += r.x; v.y += r.y; v.z += r.z; v.w += r.w;
        }
        *(float4*)(C + idx) = v;
    }
}

// ---------------- flash attention with ALiBi (causal) ----------------
// grid: (S/64, B*H), 256 threads. Dynamic smem.
#define ATT_STRIDE 65
#define ATT_SMEM_FLOATS (4 * 64 * ATT_STRIDE + 3 * 64)
#define ATT_SMEM_BYTES  (ATT_SMEM_FLOATS * 4)

__global__ void attn_kernel(const float* __restrict__ Q,
                            const float* __restrict__ Kt,
                            const float* __restrict__ Vt,
                            float* __restrict__ O) {
    extern __shared__ float sm[];
    float* Qs = sm;                      // 64 x 65
    float* Ks = Qs + 64 * ATT_STRIDE;
    float* Vs = Ks + 64 * ATT_STRIDE;
    float* Ss = Vs + 64 * ATT_STRIDE;
    float* Ms = Ss + 64 * ATT_STRIDE;    // 64 row maxes
    float* Ls = Ms + 64;                 // 64 row sums
    float* Al = Ls + 64;                 // 64 alphas

    int bh = blockIdx.y;
    int b = bh / HH, h = bh % HH;
    int qt = blockIdx.x;
    int tid = threadIdx.x;
    int tx = tid & 15, ty = tid >> 4;
    int lr = tid >> 2;                   // load row 0..63
    int lc = (tid & 3) * 16;             // load col base (16 floats)

    float slope = exp2f(-0.5f * (float)(h + 1));
    size_t base = (size_t)b * SS * DD + (size_t)h * HD;

    // load Q tile pre-scaled by 1/sqrt(HD)
    {
        const float* src = Q + base + (size_t)(qt*64 + lr) * DD + lc;
        #pragma unroll
        for (int c = 0; c < 16; c += 4) {
            float4 v = *(const float4*)(src + c);
            Qs[lr*ATT_STRIDE + lc + c + 0] = v.x * 0.125f;
            Qs[lr*ATT_STRIDE + lc + c + 1] = v.y * 0.125f;
            Qs[lr*ATT_STRIDE + lc + c + 2] = v.z * 0.125f;
            Qs[lr*ATT_STRIDE + lc + c + 3] = v.w * 0.125f;
        }
    }
    if (tid < 64) { Ms[tid] = -INFINITY; Ls[tid] = 0.f; }

    float accO[4][4] = {};

    for (int kt = 0; kt <= qt; kt++) {
        __syncthreads();   // previous Ks/Vs/Ss consumption complete
        {
            const float* ksrc = Kt + base + (size_t)(kt*64 + lr) * DD + lc;
            const float* vsrc = Vt + base + (size_t)(kt*64 + lr) * DD + lc;
            #pragma unroll
            for (int c = 0; c < 16; c += 4) {
                float4 kv = *(const float4*)(ksrc + c);
                Ks[lr*ATT_STRIDE + lc + c + 0] = kv.x;
                Ks[lr*ATT_STRIDE + lc + c + 1] = kv.y;
                Ks[lr*ATT_STRIDE + lc + c + 2] = kv.z;
                Ks[lr*ATT_STRIDE + lc + c + 3] = kv.w;
                float4 vv = *(const float4*)(vsrc + c);
                Vs[lr*ATT_STRIDE + lc + c + 0] = vv.x;
                Vs[lr*ATT_STRIDE + lc + c + 1] = vv.y;
                Vs[lr*ATT_STRIDE + lc + c + 2] = vv.z;
                Vs[lr*ATT_STRIDE + lc + c + 3] = vv.w;
            }
        }
        __syncthreads();

        // S = Qs @ Ks^T  (reduce over d)
        float accS[4][4] = {};
        for (int d = 0; d < 64; d++) {
            float ra[4], rb[4];
            #pragma unroll
            for (int i = 0; i < 4; i++) ra[i] = Qs[(ty*4 + i)*ATT_STRIDE + d];
            #pragma unroll
            for (int j = 0; j < 4; j++) rb[j] = Ks[(tx*4 + j)*ATT_STRIDE + d];
            #pragma unroll
            for (int i = 0; i < 4; i++)
                #pragma unroll
                for (int j = 0; j < 4; j++)
                    accS[i][j] = fmaf(ra[i], rb[j], accS[i][j]);
        }
        #pragma unroll
        for (int i = 0; i < 4; i++) {
            int qg = qt*64 + ty*4 + i;
            #pragma unroll
            for (int j = 0; j < 4; j++) {
                int kg = kt*64 + tx*4 + j;
                float s;
                if (kg > qg) s = -INFINITY;
                else s = accS[i][j] - slope * (float)(qg - kg);
                Ss[(ty*4 + i)*ATT_STRIDE + tx*4 + j] = s;
            }
        }
        __syncthreads();

        // online softmax per row (threads 0..63)
        if (tid < 64) {
            int r = tid;
            float rmax = -INFINITY;
            #pragma unroll 8
            for (int c = 0; c < 64; c++) rmax = fmaxf(rmax, Ss[r*ATT_STRIDE + c]);
            float mold = Ms[r];
            float mnew = fmaxf(mold, rmax);
            float alpha = (mold == -INFINITY) ? 0.f : __expf(mold - mnew);
            float rsum = 0.f;
            #pragma unroll 8
            for (int c = 0; c < 64; c++) {
                float p = __expf(Ss[r*ATT_STRIDE + c] - mnew);
                Ss[r*ATT_STRIDE + c] = p;
                rsum += p;
            }
            Ls[r] = Ls[r] * alpha + rsum;
            Ms[r] = mnew;
            Al[r] = alpha;
        }
        __syncthreads();

        // accO = accO * alpha + P @ V
        #pragma unroll
        for (int i = 0; i < 4; i++) {
            float a = Al[ty*4 + i];
            #pragma unroll
            for (int j = 0; j < 4; j++) accO[i][j] *= a;
        }
        for (int kk = 0; kk < 64; kk++) {
            float rp[4], rv[4];
            #pragma unroll
            for (int i = 0; i < 4; i++) rp[i] = Ss[(ty*4 + i)*ATT_STRIDE + kk];
            #pragma unroll
            for (int j = 0; j < 4; j++) rv[j] = Vs[kk*ATT_STRIDE + tx*4 + j];
            #pragma unroll
            for (int i = 0; i < 4; i++)
                #pragma unroll
                for (int j = 0; j < 4; j++)
                    accO[i][j] = fmaf(rp[i], rv[j], accO[i][j]);
        }
    }

    // write O (divide by row sum); layout back to [B*S, D] with col h*64+d
    #pragma unroll
    for (int i = 0; i < 4; i++) {
        float invl = 1.f / Ls[ty*4 + i];
        size_t idx = base + (size_t)(qt*64 + ty*4 + i) * DD + tx*4;
        float4 v = make_float4(accO[i][0]*invl, accO[i][1]*invl,
                               accO[i][2]*invl, accO[i][3]*invl);
        *(float4*)(O + idx) = v;
    }
}

// ---------------- SwiGLU combine: a = silu(a) * c ----------------
__global__ void swiglu_kernel(float* __restrict__ a, const float* __restrict__ c) {
    int i = blockIdx.x * 256 + threadIdx.x;
    float x = a[i];
    float s = x / (1.f + __expf(-x));
    a[i] = s * c[i];
}

// ---------------- launch ----------------
extern "C" void kernel_launch(void* const* d_in, const int* in_sizes, int n_in,
                              void* d_out, int out_size) {
    const int*   tokens = (const int*)d_in[0];
    const float* emb    = (const float*)d_in[1];
    const float* wq     = (const float*)d_in[2];
    const float* wk     = (const float*)d_in[3];
    const float* wv     = (const float*)d_in[4];
    const float* wo     = (const float*)d_in[5];
    const float* ln1_g  = (const float*)d_in[6];
    const float* ln1_b  = (const float*)d_in[7];
    const float* ln2_g  = (const float*)d_in[8];
    const float* ln2_b  = (const float*)d_in[9];
    const float* w1     = (const float*)d_in[10];
    const float* w2     = (const float*)d_in[11];
    const float* w3     = (const float*)d_in[12];
    const float* lnf_g  = (const float*)d_in[13];
    const float* lnf_b  = (const float*)d_in[14];
    const float* w_out  = (const float*)d_in[15];
    float* out = (float*)d_out;

    float *px, *ph, *pq, *pk, *pv, *po;
    cudaGetSymbolAddress((void**)&px, g_x);
    cudaGetSymbolAddress((void**)&ph, g_h);
    cudaGetSymbolAddress((void**)&pq, g_q);
    cudaGetSymbolAddress((void**)&pk, g_k);
    cudaGetSymbolAddress((void**)&pv, g_v);
    cudaGetSymbolAddress((void**)&po, g_o);

    cudaFuncSetAttribute(attn_kernel,
                         cudaFuncAttributeMaxDynamicSharedMemorySize,
                         ATT_SMEM_BYTES);

    embed_kernel<<<MM, 256>>>(tokens, emb, px);

    dim3 gg(DD/64, MM/64);
    for (int l = 0; l < LL; l++) {
        const float* Wq = wq + (size_t)l*DD*DD;
        const float* Wk = wk + (size_t)l*DD*DD;
        const float* Wv = wv + (size_t)l*DD*DD;
        const float* Wo = wo + (size_t)l*DD*DD;
        const float* W1 = w1 + (size_t)l*DD*DD;
        const float* W2 = w2 + (size_t)l*DD*DD;
        const float* W3 = w3 + (size_t)l*DD*DD;

        // attention
        ln_kernel<<<MM, 256>>>(px, ln1_g + l*DD, ln1_b + l*DD, ph);
        gemm_kernel<false><<<gg, 256>>>(ph, Wq, nullptr, pq, DD, DD);
        gemm_kernel<false><<<gg, 256>>>(ph, Wk, nullptr, pk, DD, DD);
        gemm_kernel<false><<<gg, 256>>>(ph, Wv, nullptr, pv, DD, DD);
        attn_kernel<<<dim3(SS/64, BB*HH), 256, ATT_SMEM_BYTES>>>(pq, pk, pv, po);
        gemm_kernel<true><<<gg, 256>>>(po, Wo, px, px, DD, DD);

        // SwiGLU FFN
        ln_kernel<<<MM, 256>>>(px, ln2_g + l*DD, ln2_b + l*DD, ph);
        gemm_kernel<false><<<gg, 256>>>(ph, W1, nullptr, pq, DD, DD);
        gemm_kernel<false><<<gg, 256>>>(ph, W3, nullptr, pk, DD, DD);
        swiglu_kernel<<<(MM*DD)/256, 256>>>(pq, pk);
        gemm_kernel<true><<<gg, 256>>>(pq, W2, px, px, DD, DD);
    }

    // final LN + logits
    ln_kernel<<<MM, 256>>>(px, lnf_g, lnf_b, ph);
    gemm_kernel<false><<<dim3(VV/64, MM/64), 256>>>(ph, w_out, nullptr, out, VV, DD);
}

// round 5
// speedup vs baseline: 1.9873x; 1.9873x over previous
#include <cuda_runtime.h>
#include <cuda_bf16.h>
#include <math.h>
#include <stdint.h>

// ---------------- problem constants ----------------
#define BB 2
#define SS 2048
#define DD 1024
#define HH 16
#define HD 64
#define LL 8
#define VV 32000
#define MM (BB*SS)          // 4096 rows

// ---------------- weight plane offsets (bf16 hi/lo scratch) ----------------
#define WMAT (DD*DD)                 // 1048576
#define WQ_OFF 0
#define WK_OFF (1*LL*WMAT)
#define WV_OFF (2*LL*WMAT)
#define WO_OFF (3*LL*WMAT)
#define W1_OFF (4*LL*WMAT)
#define W2_OFF (5*LL*WMAT)
#define W3_OFF (6*LL*WMAT)
#define WOUT_OFF (7*LL*WMAT)         // 58720256
#define WTOT (WOUT_OFF + VV*DD)      // 91488256

// ---------------- scratch (device globals; no cudaMalloc allowed) ----------
__device__ float g_x[MM*DD];
__device__ float g_h[MM*DD];
__device__ float g_q[MM*DD];
__device__ float g_k[MM*DD];
__device__ float g_v[MM*DD];
__device__ float g_o[MM*DD];
__device__ __nv_bfloat16 g_whi[WTOT];
__device__ __nv_bfloat16 g_wlo[WTOT];
__device__ __nv_bfloat16 g_ahi[MM*DD];
__device__ __nv_bfloat16 g_alo[MM*DD];

// ================= helpers =================
__device__ __forceinline__ uint32_t smem_u32(const void* p) {
    uint32_t a;
    asm("{ .reg .u64 t; cvta.to.shared.u64 t, %1; cvt.u32.u64 %0, t; }"
        : "=r"(a) : "l"(p));
    return a;
}

#define CP16(dst, src) \
    asm volatile("cp.async.cg.shared.global [%0], [%1], 16;" :: "r"(dst), "l"(src))
#define CP_COMMIT() asm volatile("cp.async.commit_group;" ::: "memory")
#define CP_WAIT1()  asm volatile("cp.async.wait_group 1;" ::: "memory")
#define CP_WAIT0()  asm volatile("cp.async.wait_group 0;" ::: "memory")

#define LDSM4(r, addr) \
    asm volatile("ldmatrix.sync.aligned.m8n8.x4.shared.b16 {%0,%1,%2,%3}, [%4];" \
        : "=r"((r)[0]), "=r"((r)[1]), "=r"((r)[2]), "=r"((r)[3]) : "r"(addr))

#define MMA16816(c, a, b0v, b1v) \
    asm volatile("mma.sync.aligned.m16n8k16.row.col.f32.bf16.bf16.f32 " \
        "{%0,%1,%2,%3}, {%4,%5,%6,%7}, {%8,%9}, {%0,%1,%2,%3};" \
        : "+f"((c)[0]), "+f"((c)[1]), "+f"((c)[2]), "+f"((c)[3]) \
        : "r"((a)[0]), "r"((a)[1]), "r"((a)[2]), "r"((a)[3]), "r"(b0v), "r"(b1v))

// ---------------- fp32 -> (hi, lo) bf16 split ----------------
__global__ void conv_split(const float* __restrict__ src,
                           __nv_bfloat16* __restrict__ hi,
                           __nv_bfloat16* __restrict__ lo, int n4) {
    int i = blockIdx.x * 256 + threadIdx.x;
    if (i >= n4) return;
    float4 v = ((const float4*)src)[i];
    __nv_bfloat16 h0 = __float2bfloat16(v.x);
    __nv_bfloat16 h1 = __float2bfloat16(v.y);
    __nv_bfloat16 h2 = __float2bfloat16(v.z);
    __nv_bfloat16 h3 = __float2bfloat16(v.w);
    __nv_bfloat16 l0 = __float2bfloat16(v.x - __bfloat162float(h0));
    __nv_bfloat16 l1 = __float2bfloat16(v.y - __bfloat162float(h1));
    __nv_bfloat16 l2 = __float2bfloat16(v.z - __bfloat162float(h2));
    __nv_bfloat16 l3 = __float2bfloat16(v.w - __bfloat162float(h3));
    ushort4 H = make_ushort4(__bfloat16_as_ushort(h0), __bfloat16_as_ushort(h1),
                             __bfloat16_as_ushort(h2), __bfloat16_as_ushort(h3));
    ushort4 L = make_ushort4(__bfloat16_as_ushort(l0), __bfloat16_as_ushort(l1),
                             __bfloat16_as_ushort(l2), __bfloat16_as_ushort(l3));
    ((ushort4*)hi)[i] = H;
    ((ushort4*)lo)[i] = L;
}

// ================= mma.sync split-bf16 GEMM =================
// C[M,N] = A[M,K] @ W[N,K]^T (+R), both operands K-major bf16 hi/lo planes.
// Block tile 128x128, BK=32, 256 threads (8 warps, 4(M) x 2(N), warp 32x64).
// smem per stage: 4 planes x 128 rows x 80B (32 bf16 + 8 pad) = 40960B.
#define PLANE_B 10240
#define STAGE_B (4*PLANE_B)
#define GSMEM   (2*STAGE_B)

template<bool RESID>
__global__ void __launch_bounds__(256, 1)
gemm_mma(const __nv_bfloat16* __restrict__ Ahi, const __nv_bfloat16* __restrict__ Alo,
         const __nv_bfloat16* __restrict__ Bhi, const __nv_bfloat16* __restrict__ Blo,
         const float* __restrict__ R, float* __restrict__ C, int N, int K) {
    extern __shared__ char sm_raw[];
    uint32_t sb = smem_u32(sm_raw);
    int tid = threadIdx.x, lane = tid & 31, wid = tid >> 5;
    int wm = wid & 3, wn = wid >> 2;
    int m0 = blockIdx.y * 128, n0 = blockIdx.x * 128;

    // cp.async mapping: each thread owns row tid>>1, chunks {c0, c0+1} of 4x16B
    int prow = tid >> 1;
    int pc   = (tid & 1) * 2;
    const __nv_bfloat16* srcs[4] = {Ahi, Alo, Bhi, Blo};

    int nslab = K / 32;

    // prologue: slab 0 -> stage 0
    {
        uint32_t stb = sb;
        #pragma unroll
        for (int p = 0; p < 4; p++) {
            int rb = (p < 2) ? m0 : n0;
            const __nv_bfloat16* g = srcs[p] + (size_t)(rb + prow) * K + pc * 8;
            uint32_t d = stb + p * PLANE_B + prow * 80 + pc * 16;
            CP16(d, g);
            CP16(d + 16, g + 8);
        }
        CP_COMMIT();
    }

    float acc[2][8][4] = {};
    int gq = lane >> 3, rr = lane & 7;

    for (int s = 0; s < nslab; s++) {
        if (s + 1 < nslab) {
            uint32_t stb = sb + ((s + 1) & 1) * STAGE_B;
            int k0 = (s + 1) * 32;
            #pragma unroll
            for (int p = 0; p < 4; p++) {
                int rb = (p < 2) ? m0 : n0;
                const __nv_bfloat16* g = srcs[p] + (size_t)(rb + prow) * K + k0 + pc * 8;
                uint32_t d = stb + p * PLANE_B + prow * 80 + pc * 16;
                CP16(d, g);
                CP16(d + 16, g + 8);
            }
            CP_COMMIT();
            CP_WAIT1();
        } else {
            CP_WAIT0();
        }
        __syncthreads();

        uint32_t stb = sb + (s & 1) * STAGE_B;
        #pragma unroll
        for (int ks = 0; ks < 2; ks++) {
            uint32_t ah[2][4], al[2][4], bh[4][4], bl[4][4];
            #pragma unroll
            for (int mf = 0; mf < 2; mf++) {
                int row = wm * 32 + mf * 16 + (gq & 1) * 8 + rr;
                int col = ks * 16 + (gq >> 1) * 8;
                uint32_t a = stb + row * 80 + col * 2;
                LDSM4(ah[mf], a);
                LDSM4(al[mf], a + PLANE_B);
            }
            #pragma unroll
            for (int np = 0; np < 4; np++) {
                int row = wn * 64 + np * 16 + (gq >> 1) * 8 + rr;
                int col = ks * 16 + (gq & 1) * 8;
                uint32_t a = stb + 2 * PLANE_B + row * 80 + col * 2;
                LDSM4(bh[np], a);
                LDSM4(bl[np], a + PLANE_B);
            }
            #pragma unroll
            for (int mf = 0; mf < 2; mf++) {
                #pragma unroll
                for (int np = 0; np < 4; np++) {
                    MMA16816(acc[mf][np*2],   ah[mf], bh[np][0], bh[np][1]);
                    MMA16816(acc[mf][np*2],   al[mf], bh[np][0], bh[np][1]);
                    MMA16816(acc[mf][np*2],   ah[mf], bl[np][0], bl[np][1]);
                    MMA16816(acc[mf][np*2+1], ah[mf], bh[np][2], bh[np][3]);
                    MMA16816(acc[mf][np*2+1], al[mf], bh[np][2], bh[np][3]);
                    MMA16816(acc[mf][np*2+1], ah[mf], bl[np][2], bl[np][3]);
                }
            }
        }
        __syncthreads();
    }

    // epilogue: c0,c1 at (row, col..col+1); c2,c3 at (row+8, ...)
    int rbase = m0 + wm * 32 + (lane >> 2);
    int cbase = n0 + wn * 64 + (lane & 3) * 2;
    #pragma unroll
    for (int mf = 0; mf < 2; mf++) {
        #pragma unroll
        for (int nf = 0; nf < 8; nf++) {
            int row = rbase + mf * 16;
            int col = cbase + nf * 8;
            float2 v0 = make_float2(acc[mf][nf][0], acc[mf][nf][1]);
            float2 v1 = make_float2(acc[mf][nf][2], acc[mf][nf][3]);
            if (RESID) {
                float2 r0 = *(const float2*)(R + (size_t)row * N + col);
                float2 r1 = *(const float2*)(R + (size_t)(row + 8) * N + col);
                v0.x += r0.x; v0.y += r0.y;
                v1.x += r1.x; v1.y += r1.y;
            }
            *(float2*)(C + (size_t)row * N + col) = v0;
            *(float2*)(C + (size_t)(row + 8) * N + col) = v1;
        }
    }
}

// ---------------- embedding lookup ----------------
__global__ void embed_kernel(const int* __restrict__ tokens,
                             const float* __restrict__ emb,
                             float* __restrict__ x) {
    int row = blockIdx.x;
    int tok = tokens[row];
    const float4* src = (const float4*)(emb + (size_t)tok * DD);
    float4* dst = (float4*)(x + (size_t)row * DD);
    for (int i = threadIdx.x; i < DD/4; i += blockDim.x) dst[i] = src[i];
}

// ---------------- layernorm (one block per row) ----------------
__global__ void ln_kernel(const float* __restrict__ x,
                          const float* __restrict__ gw,
                          const float* __restrict__ bw,
                          float* __restrict__ out) {
    int row = blockIdx.x;
    const float* xr = x + (size_t)row * DD;
    float s = 0.f, s2 = 0.f;
    for (int i = threadIdx.x; i < DD; i += 256) {
        float v = xr[i];
        s += v;
        s2 = fmaf(v, v, s2);
    }
    __shared__ float rs[8], rs2[8];
    #pragma unroll
    for (int o = 16; o > 0; o >>= 1) {
        s  += __shfl_down_sync(0xffffffffu, s,  o);
        s2 += __shfl_down_sync(0xffffffffu, s2, o);
    }
    int w = threadIdx.x >> 5;
    if ((threadIdx.x & 31) == 0) { rs[w] = s; rs2[w] = s2; }
    __syncthreads();
    __shared__ float mean_s, rstd_s;
    if (threadIdx.x == 0) {
        float ts = 0.f, ts2 = 0.f;
        #pragma unroll
        for (int i = 0; i < 8; i++) { ts += rs[i]; ts2 += rs2[i]; }
        float m = ts / (float)DD;
        float var = ts2 / (float)DD - m * m;
        mean_s = m;
        rstd_s = rsqrtf(var + 1e-5f);
    }
    __syncthreads();
    float m = mean_s, r = rstd_s;
    float* orow = out + (size_t)row * DD;
    for (int i = threadIdx.x; i < DD; i += 256)
        orow[i] = (xr[i] - m) * r * gw[i] + bw[i];
}

// ---------------- flash attention with ALiBi (causal) ----------------
#define ATT_STRIDE 65
#define ATT_SMEM_FLOATS (4 * 64 * ATT_STRIDE + 3 * 64)
#define ATT_SMEM_BYTES  (ATT_SMEM_FLOATS * 4)

__global__ void attn_kernel(const float* __restrict__ Q,
                            const float* __restrict__ Kt,
                            const float* __restrict__ Vt,
                            float* __restrict__ O) {
    extern __shared__ float sm[];
    float* Qs = sm;
    float* Ks = Qs + 64 * ATT_STRIDE;
    float* Vs = Ks + 64 * ATT_STRIDE;
    float* Ss = Vs + 64 * ATT_STRIDE;
    float* Ms = Ss + 64 * ATT_STRIDE;
    float* Ls = Ms + 64;
    float* Al = Ls + 64;

    int bh = blockIdx.y;
    int b = bh / HH, h = bh % HH;
    int qt = blockIdx.x;
    int tid = threadIdx.x;
    int tx = tid & 15, ty = tid >> 4;
    int lr = tid >> 2;
    int lc = (tid & 3) * 16;

    float slope = exp2f(-0.5f * (float)(h + 1));
    size_t base = (size_t)b * SS * DD + (size_t)h * HD;

    {
        const float* src = Q + base + (size_t)(qt*64 + lr) * DD + lc;
        #pragma unroll
        for (int c = 0; c < 16; c += 4) {
            float4 v = *(const float4*)(src + c);
            Qs[lr*ATT_STRIDE + lc + c + 0] = v.x * 0.125f;
            Qs[lr*ATT_STRIDE + lc + c + 1] = v.y * 0.125f;
            Qs[lr*ATT_STRIDE + lc + c + 2] = v.z * 0.125f;
            Qs[lr*ATT_STRIDE + lc + c + 3] = v.w * 0.125f;
        }
    }
    if (tid < 64) { Ms[tid] = -INFINITY; Ls[tid] = 0.f; }

    float accO[4][4] = {};

    for (int kt = 0; kt <= qt; kt++) {
        __syncthreads();
        {
            const float* ksrc = Kt + base + (size_t)(kt*64 + lr) * DD + lc;
            const float* vsrc = Vt + base + (size_t)(kt*64 + lr) * DD + lc;
            #pragma unroll
            for (int c = 0; c < 16; c += 4) {
                float4 kv = *(const float4*)(ksrc + c);
                Ks[lr*ATT_STRIDE + lc + c + 0] = kv.x;
                Ks[lr*ATT_STRIDE + lc + c + 1] = kv.y;
                Ks[lr*ATT_STRIDE + lc + c + 2] = kv.z;
                Ks[lr*ATT_STRIDE + lc + c + 3] = kv.w;
                float4 vv = *(const float4*)(vsrc + c);
                Vs[lr*ATT_STRIDE + lc + c + 0] = vv.x;
                Vs[lr*ATT_STRIDE + lc + c + 1] = vv.y;
                Vs[lr*ATT_STRIDE + lc + c + 2] = vv.z;
                Vs[lr*ATT_STRIDE + lc + c + 3] = vv.w;
            }
        }
        __syncthreads();

        float accS[4][4] = {};
        for (int d = 0; d < 64; d++) {
            float ra[4], rb[4];
            #pragma unroll
            for (int i = 0; i < 4; i++) ra[i] = Qs[(ty*4 + i)*ATT_STRIDE + d];
            #pragma unroll
            for (int j = 0; j < 4; j++) rb[j] = Ks[(tx*4 + j)*ATT_STRIDE + d];
            #pragma unroll
            for (int i = 0; i < 4; i++)
                #pragma unroll
                for (int j = 0; j < 4; j++)
                    accS[i][j] = fmaf(ra[i], rb[j], accS[i][j]);
        }
        #pragma unroll
        for (int i = 0; i < 4; i++) {
            int qg = qt*64 + ty*4 + i;
            #pragma unroll
            for (int j = 0; j < 4; j++) {
                int kg = kt*64 + tx*4 + j;
                float s;
                if (kg > qg) s = -INFINITY;
                else s = accS[i][j] - slope * (float)(qg - kg);
                Ss[(ty*4 + i)*ATT_STRIDE + tx*4 + j] = s;
            }
        }
        __syncthreads();

        if (tid < 64) {
            int r = tid;
            float rmax = -INFINITY;
            #pragma unroll 8
            for (int c = 0; c < 64; c++) rmax = fmaxf(rmax, Ss[r*ATT_STRIDE + c]);
            float mold = Ms[r];
            float mnew = fmaxf(mold, rmax);
            float alpha = (mold == -INFINITY) ? 0.f : __expf(mold - mnew);
            float rsum = 0.f;
            #pragma unroll 8
            for (int c = 0; c < 64; c++) {
                float p = __expf(Ss[r*ATT_STRIDE + c] - mnew);
                Ss[r*ATT_STRIDE + c] = p;
                rsum += p;
            }
            Ls[r] = Ls[r] * alpha + rsum;
            Ms[r] = mnew;
            Al[r] = alpha;
        }
        __syncthreads();

        #pragma unroll
        for (int i = 0; i < 4; i++) {
            float a = Al[ty*4 + i];
            #pragma unroll
            for (int j = 0; j < 4; j++) accO[i][j] *= a;
        }
        for (int kk = 0; kk < 64; kk++) {
            float rp[4], rv[4];
            #pragma unroll
            for (int i = 0; i < 4; i++) rp[i] = Ss[(ty*4 + i)*ATT_STRIDE + kk];
            #pragma unroll
            for (int j = 0; j < 4; j++) rv[j] = Vs[kk*ATT_STRIDE + tx*4 + j];
            #pragma unroll
            for (int i = 0; i < 4; i++)
                #pragma unroll
                for (int j = 0; j < 4; j++)
                    accO[i][j] = fmaf(rp[i], rv[j], accO[i][j]);
        }
    }

    #pragma unroll
    for (int i = 0; i < 4; i++) {
        float invl = 1.f / Ls[ty*4 + i];
        size_t idx = base + (size_t)(qt*64 + ty*4 + i) * DD + tx*4;
        float4 v = make_float4(accO[i][0]*invl, accO[i][1]*invl,
                               accO[i][2]*invl, accO[i][3]*invl);
        *(float4*)(O + idx) = v;
    }
}

// ---------------- SwiGLU combine: a = silu(a) * c ----------------
__global__ void swiglu_kernel(float* __restrict__ a, const float* __restrict__ c) {
    int i = blockIdx.x * 256 + threadIdx.x;
    float x = a[i];
    float s = x / (1.f + __expf(-x));
    a[i] = s * c[i];
}

// ---------------- launch ----------------
extern "C" void kernel_launch(void* const* d_in, const int* in_sizes, int n_in,
                              void* d_out, int out_size) {
    const int*   tokens = (const int*)d_in[0];
    const float* emb    = (const float*)d_in[1];
    const float* wq     = (const float*)d_in[2];
    const float* wk     = (const float*)d_in[3];
    const float* wv     = (const float*)d_in[4];
    const float* wo     = (const float*)d_in[5];
    const float* ln1_g  = (const float*)d_in[6];
    const float* ln1_b  = (const float*)d_in[7];
    const float* ln2_g  = (const float*)d_in[8];
    const float* ln2_b  = (const float*)d_in[9];
    const float* w1     = (const float*)d_in[10];
    const float* w2     = (const float*)d_in[11];
    const float* w3     = (const float*)d_in[12];
    const float* lnf_g  = (const float*)d_in[13];
    const float* lnf_b  = (const float*)d_in[14];
    const float* w_out  = (const float*)d_in[15];
    float* out = (float*)d_out;

    float *px, *ph, *pq, *pk, *pv, *po;
    cudaGetSymbolAddress((void**)&px, g_x);
    cudaGetSymbolAddress((void**)&ph, g_h);
    cudaGetSymbolAddress((void**)&pq, g_q);
    cudaGetSymbolAddress((void**)&pk, g_k);
    cudaGetSymbolAddress((void**)&pv, g_v);
    cudaGetSymbolAddress((void**)&po, g_o);
    __nv_bfloat16 *whi, *wlo, *ahi, *alo;
    cudaGetSymbolAddress((void**)&whi, g_whi);
    cudaGetSymbolAddress((void**)&wlo, g_wlo);
    cudaGetSymbolAddress((void**)&ahi, g_ahi);
    cudaGetSymbolAddress((void**)&alo, g_alo);

    cudaFuncSetAttribute(attn_kernel,
                         cudaFuncAttributeMaxDynamicSharedMemorySize,
                         ATT_SMEM_BYTES);
    cudaFuncSetAttribute(gemm_mma<false>,
                         cudaFuncAttributeMaxDynamicSharedMemorySize, GSMEM);
    cudaFuncSetAttribute(gemm_mma<true>,
                         cudaFuncAttributeMaxDynamicSharedMemorySize, GSMEM);

    // ---- convert all weights to bf16 hi/lo planes ----
    {
        int n4w = (LL * WMAT) / 4;               // per 8-layer weight tensor
        conv_split<<<n4w/256, 256>>>(wq, whi + WQ_OFF, wlo + WQ_OFF, n4w);
        conv_split<<<n4w/256, 256>>>(wk, whi + WK_OFF, wlo + WK_OFF, n4w);
        conv_split<<<n4w/256, 256>>>(wv, whi + WV_OFF, wlo + WV_OFF, n4w);
        conv_split<<<n4w/256, 256>>>(wo, whi + WO_OFF, wlo + WO_OFF, n4w);
        conv_split<<<n4w/256, 256>>>(w1, whi + W1_OFF, wlo + W1_OFF, n4w);
        conv_split<<<n4w/256, 256>>>(w2, whi + W2_OFF, wlo + W2_OFF, n4w);
        conv_split<<<n4w/256, 256>>>(w3, whi + W3_OFF, wlo + W3_OFF, n4w);
        int n4o = (VV * DD) / 4;
        conv_split<<<n4o/256, 256>>>(w_out, whi + WOUT_OFF, wlo + WOUT_OFF, n4o);
    }

    embed_kernel<<<MM, 256>>>(tokens, emb, px);

    const int n4a = (MM * DD) / 4;
    dim3 gg(DD/128, MM/128);
    for (int l = 0; l < LL; l++) {
        size_t lo_off = (size_t)l * WMAT;

        // attention
        ln_kernel<<<MM, 256>>>(px, ln1_g + l*DD, ln1_b + l*DD, ph);
        conv_split<<<n4a/256, 256>>>(ph, ahi, alo, n4a);
        gemm_mma<false><<<gg, 256, GSMEM>>>(ahi, alo, whi + WQ_OFF + lo_off,
                                            wlo + WQ_OFF + lo_off, nullptr, pq, DD, DD);
        gemm_mma<false><<<gg, 256, GSMEM>>>(ahi, alo, whi + WK_OFF + lo_off,
                                            wlo + WK_OFF + lo_off, nullptr, pk, DD, DD);
        gemm_mma<false><<<gg, 256, GSMEM>>>(ahi, alo, whi + WV_OFF + lo_off,
                                            wlo + WV_OFF + lo_off, nullptr, pv, DD, DD);
        attn_kernel<<<dim3(SS/64, BB*HH), 256, ATT_SMEM_BYTES>>>(pq, pk, pv, po);
        conv_split<<<n4a/256, 256>>>(po, ahi, alo, n4a);
        gemm_mma<true><<<gg, 256, GSMEM>>>(ahi, alo, whi + WO_OFF + lo_off,
                                           wlo + WO_OFF + lo_off, px, px, DD, DD);

        // SwiGLU FFN
        ln_kernel<<<MM, 256>>>(px, ln2_g + l*DD, ln2_b + l*DD, ph);
        conv_split<<<n4a/256, 256>>>(ph, ahi, alo, n4a);
        gemm_mma<false><<<gg, 256, GSMEM>>>(ahi, alo, whi + W1_OFF + lo_off,
                                            wlo + W1_OFF + lo_off, nullptr, pq, DD, DD);
        gemm_mma<false><<<gg, 256, GSMEM>>>(ahi, alo, whi + W3_OFF + lo_off,
                                            wlo + W3_OFF + lo_off, nullptr, pk, DD, DD);
        swiglu_kernel<<<(MM*DD)/256, 256>>>(pq, pk);
        conv_split<<<n4a/256, 256>>>(pq, ahi, alo, n4a);
        gemm_mma<true><<<gg, 256, GSMEM>>>(ahi, alo, whi + W2_OFF + lo_off,
                                           wlo + W2_OFF + lo_off, px, px, DD, DD);
    }

    // final LN + logits
    ln_kernel<<<MM, 256>>>(px, lnf_g, lnf_b, ph);
    conv_split<<<n4a/256, 256>>>(ph, ahi, alo, n4a);
    gemm_mma<false><<<dim3(VV/128, MM/128), 256, GSMEM>>>(
        ahi, alo, whi + WOUT_OFF, wlo + WOUT_OFF, nullptr, out, VV, DD);
}

// round 6
// speedup vs baseline: 2.8969x; 1.4577x over previous
#include <cuda_runtime.h>
#include <cuda_bf16.h>
#include <math.h>
#include <stdint.h>

// ---------------- problem constants ----------------
#define BB 2
#define SS 2048
#define DD 1024
#define HH 16
#define HD 64
#define LL 8
#define VV 32000
#define MM (BB*SS)          // 4096 rows

// ---------------- weight plane offsets (bf16 hi/lo scratch) ----------------
#define WMAT (DD*DD)
#define WQ_OFF 0
#define WK_OFF (1*LL*WMAT)
#define WV_OFF (2*LL*WMAT)
#define WO_OFF (3*LL*WMAT)
#define W1_OFF (4*LL*WMAT)
#define W2_OFF (5*LL*WMAT)
#define W3_OFF (6*LL*WMAT)
#define WOUT_OFF (7*LL*WMAT)
#define WTOT (WOUT_OFF + VV*DD)

// ---------------- scratch (device globals; no cudaMalloc allowed) ----------
__device__ float g_x[MM*DD];
__device__ float g_q[MM*DD];
__device__ float g_k[MM*DD];
__device__ float g_v[MM*DD];
__device__ __nv_bfloat16 g_whi[WTOT];
__device__ __nv_bfloat16 g_wlo[WTOT];
__device__ __nv_bfloat16 g_ahi[MM*DD];
__device__ __nv_bfloat16 g_alo[MM*DD];

// ================= helpers =================
__device__ __forceinline__ uint32_t smem_u32(const void* p) {
    uint32_t a;
    asm("{ .reg .u64 t; cvta.to.shared.u64 t, %1; cvt.u32.u64 %0, t; }"
        : "=r"(a) : "l"(p));
    return a;
}

#define CP16(dst, src) \
    asm volatile("cp.async.cg.shared.global [%0], [%1], 16;" :: "r"(dst), "l"(src))
#define CP_COMMIT() asm volatile("cp.async.commit_group;" ::: "memory")
#define CP_WAIT1()  asm volatile("cp.async.wait_group 1;" ::: "memory")
#define CP_WAIT0()  asm volatile("cp.async.wait_group 0;" ::: "memory")

#define LDSM4(r, addr) \
    asm volatile("ldmatrix.sync.aligned.m8n8.x4.shared.b16 {%0,%1,%2,%3}, [%4];" \
        : "=r"((r)[0]), "=r"((r)[1]), "=r"((r)[2]), "=r"((r)[3]) : "r"(addr))

#define MMA16816(c, a, b0v, b1v) \
    asm volatile("mma.sync.aligned.m16n8k16.row.col.f32.bf16.bf16.f32 " \
        "{%0,%1,%2,%3}, {%4,%5,%6,%7}, {%8,%9}, {%0,%1,%2,%3};" \
        : "+f"((c)[0]), "+f"((c)[1]), "+f"((c)[2]), "+f"((c)[3]) \
        : "r"((a)[0]), "r"((a)[1]), "r"((a)[2]), "r"((a)[3]), "r"(b0v), "r"(b1v))

__device__ __forceinline__ void split1(float x, __nv_bfloat16& h, __nv_bfloat16& l) {
    h = __float2bfloat16(x);
    l = __float2bfloat16(x - __bfloat162float(h));
}

// ---------------- fp32 -> (hi, lo) bf16 split (weights) ----------------
__global__ void conv_split(const float* __restrict__ src,
                           __nv_bfloat16* __restrict__ hi,
                           __nv_bfloat16* __restrict__ lo, int n4) {
    int i = blockIdx.x * 256 + threadIdx.x;
    if (i >= n4) return;
    float4 v = ((const float4*)src)[i];
    __nv_bfloat16 h0, h1, h2, h3, l0, l1, l2, l3;
    split1(v.x, h0, l0); split1(v.y, h1, l1);
    split1(v.z, h2, l2); split1(v.w, h3, l3);
    ((ushort4*)hi)[i] = make_ushort4(__bfloat16_as_ushort(h0), __bfloat16_as_ushort(h1),
                                     __bfloat16_as_ushort(h2), __bfloat16_as_ushort(h3));
    ((ushort4*)lo)[i] = make_ushort4(__bfloat16_as_ushort(l0), __bfloat16_as_ushort(l1),
                                     __bfloat16_as_ushort(l2), __bfloat16_as_ushort(l3));
}

// ================= mma.sync split-bf16 GEMM =================
// C[M,N] = A[M,K] @ W[N,K]^T (+R). 128x128 tile, BK=32, 256 thr, occ 2.
#define PLANE_B 10240
#define STAGE_B (4*PLANE_B)
#define GSMEM   (2*STAGE_B)

template<bool RESID>
__global__ void __launch_bounds__(256, 2)
gemm_mma(const __nv_bfloat16* __restrict__ Ahi, const __nv_bfloat16* __restrict__ Alo,
         const __nv_bfloat16* __restrict__ Bhi, const __nv_bfloat16* __restrict__ Blo,
         const float* __restrict__ R, float* __restrict__ C, int N, int K) {
    extern __shared__ char sm_raw[];
    uint32_t sb = smem_u32(sm_raw);
    int tid = threadIdx.x, lane = tid & 31, wid = tid >> 5;
    int wm = wid & 3, wn = wid >> 2;
    int m0 = blockIdx.y * 128, n0 = blockIdx.x * 128;

    int prow = tid >> 1;
    int pc   = (tid & 1) * 2;
    const __nv_bfloat16* srcs[4] = {Ahi, Alo, Bhi, Blo};

    int nslab = K / 32;

    {   // prologue
        #pragma unroll
        for (int p = 0; p < 4; p++) {
            int rb = (p < 2) ? m0 : n0;
            const __nv_bfloat16* g = srcs[p] + (size_t)(rb + prow) * K + pc * 8;
            uint32_t d = sb + p * PLANE_B + prow * 80 + pc * 16;
            CP16(d, g);
            CP16(d + 16, g + 8);
        }
        CP_COMMIT();
    }

    float acc[2][8][4] = {};
    int gq = lane >> 3, rr = lane & 7;

    for (int s = 0; s < nslab; s++) {
        if (s + 1 < nslab) {
            uint32_t stb = sb + ((s + 1) & 1) * STAGE_B;
            int k0 = (s + 1) * 32;
            #pragma unroll
            for (int p = 0; p < 4; p++) {
                int rb = (p < 2) ? m0 : n0;
                const __nv_bfloat16* g = srcs[p] + (size_t)(rb + prow) * K + k0 + pc * 8;
                uint32_t d = stb + p * PLANE_B + prow * 80 + pc * 16;
                CP16(d, g);
                CP16(d + 16, g + 8);
            }
            CP_COMMIT();
            CP_WAIT1();
        } else {
            CP_WAIT0();
        }
        __syncthreads();

        uint32_t stb = sb + (s & 1) * STAGE_B;
        #pragma unroll
        for (int ks = 0; ks < 2; ks++) {
            uint32_t ah[2][4], al[2][4];
            #pragma unroll
            for (int mf = 0; mf < 2; mf++) {
                int row = wm * 32 + mf * 16 + (gq & 1) * 8 + rr;
                int col = ks * 16 + (gq >> 1) * 8;
                uint32_t a = stb + row * 80 + col * 2;
                LDSM4(ah[mf], a);
                LDSM4(al[mf], a + PLANE_B);
            }
            #pragma unroll
            for (int np = 0; np < 4; np++) {
                uint32_t bh[4], bl[4];
                int row = wn * 64 + np * 16 + (gq >> 1) * 8 + rr;
                int col = ks * 16 + (gq & 1) * 8;
                uint32_t a = stb + 2 * PLANE_B + row * 80 + col * 2;
                LDSM4(bh, a);
                LDSM4(bl, a + PLANE_B);
                #pragma unroll
                for (int mf = 0; mf < 2; mf++) {
                    MMA16816(acc[mf][np*2],   ah[mf], bh[0], bh[1]);
                    MMA16816(acc[mf][np*2],   al[mf], bh[0], bh[1]);
                    MMA16816(acc[mf][np*2],   ah[mf], bl[0], bl[1]);
                    MMA16816(acc[mf][np*2+1], ah[mf], bh[2], bh[3]);
                    MMA16816(acc[mf][np*2+1], al[mf], bh[2], bh[3]);
                    MMA16816(acc[mf][np*2+1], ah[mf], bl[2], bl[3]);
                }
            }
        }
        __syncthreads();
    }

    int rbase = m0 + wm * 32 + (lane >> 2);
    int cbase = n0 + wn * 64 + (lane & 3) * 2;
    #pragma unroll
    for (int mf = 0; mf < 2; mf++) {
        #pragma unroll
        for (int nf = 0; nf < 8; nf++) {
            int row = rbase + mf * 16;
            int col = cbase + nf * 8;
            float2 v0 = make_float2(acc[mf][nf][0], acc[mf][nf][1]);
            float2 v1 = make_float2(acc[mf][nf][2], acc[mf][nf][3]);
            if (RESID) {
                float2 r0 = *(const float2*)(R + (size_t)row * N + col);
                float2 r1 = *(const float2*)(R + (size_t)(row + 8) * N + col);
                v0.x += r0.x; v0.y += r0.y;
                v1.x += r1.x; v1.y += r1.y;
            }
            *(float2*)(C + (size_t)row * N + col) = v0;
            *(float2*)(C + (size_t)(row + 8) * N + col) = v1;
        }
    }
}

// ================= mma.sync flash attention (split bf16) =================
// 64 q-rows per CTA, 4 warps (16 rows each), 64-key tiles, HD=64.
// smem planes: Qh Ql Kh Kl Vh Vl, each [64][72] bf16 (V transposed: [hd][key]).
#define ALD 72
#define APLANE (64*ALD*2)        // 9216 B
#define ASMEM  (6*APLANE)        // 55296 B

__global__ void __launch_bounds__(128)
attn_mma(const float* __restrict__ Q, const float* __restrict__ Kg,
         const float* __restrict__ Vg,
         __nv_bfloat16* __restrict__ Ohi, __nv_bfloat16* __restrict__ Olo) {
    extern __shared__ char asmr[];
    uint32_t sb = smem_u32(asmr);
    const uint32_t QH = sb, QL = sb + APLANE, KH = sb + 2*APLANE,
                   KL = sb + 3*APLANE, VH = sb + 4*APLANE, VL = sb + 5*APLANE;

    int tid = threadIdx.x, lane = tid & 31, w = tid >> 5;
    int gq = lane >> 3, rr = lane & 7;
    int bh = blockIdx.y;
    int b = bh / HH, h = bh % HH;
    int qt = blockIdx.x;
    float slope = exp2f(-0.5f * (float)(h + 1));

    int lrow = tid >> 4;          // 0..7
    int lcol = (tid & 15) * 4;    // 0..60

    // ---- load Q tile (scaled by 1/8), split into smem ----
    #pragma unroll
    for (int pass = 0; pass < 8; pass++) {
        int row = lrow + pass * 8;
        size_t gaddr = (size_t)(b*SS + qt*64 + row) * DD + h*HD + lcol;
        float4 v = *(const float4*)(Q + gaddr);
        __nv_bfloat16 h0,h1,h2,h3,l0,l1,l2,l3;
        split1(v.x*0.125f, h0, l0); split1(v.y*0.125f, h1, l1);
        split1(v.z*0.125f, h2, l2); split1(v.w*0.125f, h3, l3);
        uint32_t off = (row*ALD + lcol) * 2;
        *(ushort4*)(asmr + (QH - sb) + off) =
            make_ushort4(__bfloat16_as_ushort(h0), __bfloat16_as_ushort(h1),
                         __bfloat16_as_ushort(h2), __bfloat16_as_ushort(h3));
        *(ushort4*)(asmr + (QL - sb) + off) =
            make_ushort4(__bfloat16_as_ushort(l0), __bfloat16_as_ushort(l1),
                         __bfloat16_as_ushort(l2), __bfloat16_as_ushort(l3));
    }
    __syncthreads();

    // ---- Q fragments (per warp: rows w*16..+15) ----
    uint32_t qh[4][4], ql[4][4];
    #pragma unroll
    for (int kk = 0; kk < 4; kk++) {
        uint32_t off = ((w*16 + (gq & 1)*8 + rr)*ALD + kk*16 + (gq >> 1)*8) * 2;
        LDSM4(qh[kk], QH + off);
        LDSM4(ql[kk], QL + off);
    }

    float m0r = -INFINITY, m1r = -INFINITY, l0s = 0.f, l1s = 0.f;
    float o[8][4] = {};
    int qg0 = qt*64 + w*16 + (lane >> 2);
    int qg1 = qg0 + 8;

    for (int kt = 0; kt <= qt; kt++) {
        __syncthreads();
        // load K (split, row-major) and V (split, transposed)
        #pragma unroll
        for (int pass = 0; pass < 8; pass++) {
            int row = lrow + pass * 8;
            size_t gaddr = (size_t)(b*SS + kt*64 + row) * DD + h*HD + lcol;
            float4 kv = *(const float4*)(Kg + gaddr);
            __nv_bfloat16 h0,h1,h2,h3,l0,l1,l2,l3;
            split1(kv.x, h0, l0); split1(kv.y, h1, l1);
            split1(kv.z, h2, l2); split1(kv.w, h3, l3);
            uint32_t off = (row*ALD + lcol) * 2;
            *(ushort4*)(asmr + (KH - sb) + off) =
                make_ushort4(__bfloat16_as_ushort(h0), __bfloat16_as_ushort(h1),
                             __bfloat16_as_ushort(h2), __bfloat16_as_ushort(h3));
            *(ushort4*)(asmr + (KL - sb) + off) =
                make_ushort4(__bfloat16_as_ushort(l0), __bfloat16_as_ushort(l1),
                             __bfloat16_as_ushort(l2), __bfloat16_as_ushort(l3));
            float4 vv = *(const float4*)(Vg + gaddr);
            float vs[4] = {vv.x, vv.y, vv.z, vv.w};
            #pragma unroll
            for (int i = 0; i < 4; i++) {
                __nv_bfloat16 vh, vl;
                split1(vs[i], vh, vl);
                uint32_t toff = ((lcol + i)*ALD + row) * 2;
                *(__nv_bfloat16*)(asmr + (VH - sb) + toff) = vh;
                *(__nv_bfloat16*)(asmr + (VL - sb) + toff) = vl;
            }
        }
        __syncthreads();

        // ---- S = Q @ K^T ----
        float s[8][4] = {};
        #pragma unroll
        for (int kk = 0; kk < 4; kk++) {
            #pragma unroll
            for (int np = 0; np < 4; np++) {
                uint32_t kb[4], kl2[4];
                uint32_t off = ((np*16 + (gq >> 1)*8 + rr)*ALD + kk*16 + (gq & 1)*8) * 2;
                LDSM4(kb, KH + off);
                LDSM4(kl2, KL + off);
                MMA16816(s[np*2],   qh[kk], kb[0], kb[1]);
                MMA16816(s[np*2],   ql[kk], kb[0], kb[1]);
                MMA16816(s[np*2],   qh[kk], kl2[0], kl2[1]);
                MMA16816(s[np*2+1], qh[kk], kb[2], kb[3]);
                MMA16816(s[np*2+1], ql[kk], kb[2], kb[3]);
                MMA16816(s[np*2+1], qh[kk], kl2[2], kl2[3]);
            }
        }

        // ---- ALiBi bias + causal mask ----
        #pragma unroll
        for (int nf = 0; nf < 8; nf++) {
            #pragma unroll
            for (int c = 0; c < 2; c++) {
                int kg = kt*64 + nf*8 + (lane & 3)*2 + c;
                s[nf][c]   = (kg <= qg0) ? s[nf][c]   + slope*(float)(kg - qg0) : -1e30f;
                s[nf][2+c] = (kg <= qg1) ? s[nf][2+c] + slope*(float)(kg - qg1) : -1e30f;
            }
        }

        // ---- online softmax ----
        float mx0 = -1e30f, mx1 = -1e30f;
        #pragma unroll
        for (int nf = 0; nf < 8; nf++) {
            mx0 = fmaxf(mx0, fmaxf(s[nf][0], s[nf][1]));
            mx1 = fmaxf(mx1, fmaxf(s[nf][2], s[nf][3]));
        }
        #pragma unroll
        for (int off = 1; off <= 2; off <<= 1) {
            mx0 = fmaxf(mx0, __shfl_xor_sync(0xffffffffu, mx0, off));
            mx1 = fmaxf(mx1, __shfl_xor_sync(0xffffffffu, mx1, off));
        }
        float mn0 = fmaxf(m0r, mx0), mn1 = fmaxf(m1r, mx1);
        float al0 = __expf(m0r - mn0), al1 = __expf(m1r - mn1);
        float rs0 = 0.f, rs1 = 0.f;
        #pragma unroll
        for (int nf = 0; nf < 8; nf++) {
            s[nf][0] = __expf(s[nf][0] - mn0);
            s[nf][1] = __expf(s[nf][1] - mn0);
            s[nf][2] = __expf(s[nf][2] - mn1);
            s[nf][3] = __expf(s[nf][3] - mn1);
            rs0 += s[nf][0] + s[nf][1];
            rs1 += s[nf][2] + s[nf][3];
        }
        #pragma unroll
        for (int off = 1; off <= 2; off <<= 1) {
            rs0 += __shfl_xor_sync(0xffffffffu, rs0, off);
            rs1 += __shfl_xor_sync(0xffffffffu, rs1, off);
        }
        l0s = l0s * al0 + rs0;
        l1s = l1s * al1 + rs1;
        m0r = mn0; m1r = mn1;

        #pragma unroll
        for (int nf = 0; nf < 8; nf++) {
            o[nf][0] *= al0; o[nf][1] *= al0;
            o[nf][2] *= al1; o[nf][3] *= al1;
        }

        // ---- O += P @ V (P split on the fly) ----
        #pragma unroll
        for (int kk = 0; kk < 4; kk++) {
            uint32_t pah[4], pal[4];
            #pragma unroll
            for (int half = 0; half < 2; half++) {
                float* sv = s[2*kk + half];
                __nv_bfloat162 h01 = __floats2bfloat162_rn(sv[0], sv[1]);
                __nv_bfloat162 h23 = __floats2bfloat162_rn(sv[2], sv[3]);
                __nv_bfloat162 L01 = __floats2bfloat162_rn(
                    sv[0] - __bfloat162float(__low2bfloat16(h01)),
                    sv[1] - __bfloat162float(__high2bfloat16(h01)));
                __nv_bfloat162 L23 = __floats2bfloat162_rn(
                    sv[2] - __bfloat162float(__low2bfloat16(h23)),
                    sv[3] - __bfloat162float(__high2bfloat16(h23)));
                pah[half*2 + 0] = *(uint32_t*)&h01;   // rows r
                pah[half*2 + 1] = *(uint32_t*)&h23;   // rows r+8
                pal[half*2 + 0] = *(uint32_t*)&L01;
                pal[half*2 + 1] = *(uint32_t*)&L23;
            }
            // reorder to A-frag: a0(r,klo) a1(r+8,klo) a2(r,khi) a3(r+8,khi)
            uint32_t Ah[4] = {pah[0], pah[1], pah[2], pah[3]};
            uint32_t Al2[4] = {pal[0], pal[1], pal[2], pal[3]};
            #pragma unroll
            for (int np = 0; np < 4; np++) {
                uint32_t vb[4], vl2[4];
                uint32_t off = ((np*16 + (gq >> 1)*8 + rr)*ALD + kk*16 + (gq & 1)*8) * 2;
                LDSM4(vb, VH + off);
                LDSM4(vl2, VL + off);
                MMA16816(o[np*2],   Ah,  vb[0], vb[1]);
                MMA16816(o[np*2],   Al2, vb[0], vb[1]);
                MMA16816(o[np*2],   Ah,  vl2[0], vl2[1]);
                MMA16816(o[np*2+1], Ah,  vb[2], vb[3]);
                MMA16816(o[np*2+1], Al2, vb[2], vb[3]);
                MMA16816(o[np*2+1], Ah,  vl2[2], vl2[3]);
            }
        }
    }

    // ---- epilogue: O/l, split to bf16 hi/lo global planes ----
    float inv0 = 1.f / l0s, inv1 = 1.f / l1s;
    int row0 = b*SS + qt*64 + w*16 + (lane >> 2);
    int colb = h*HD + (lane & 3)*2;
    #pragma unroll
    for (int nf = 0; nf < 8; nf++) {
        float v0 = o[nf][0]*inv0, v1 = o[nf][1]*inv0;
        float v2 = o[nf][2]*inv1, v3 = o[nf][3]*inv1;
        size_t a0 = (size_t)row0 * DD + colb + nf*8;
        size_t a1 = (size_t)(row0 + 8) * DD + colb + nf*8;
        __nv_bfloat162 h01 = __floats2bfloat162_rn(v0, v1);
        __nv_bfloat162 h23 = __floats2bfloat162_rn(v2, v3);
        __nv_bfloat162 L01 = __floats2bfloat162_rn(
            v0 - __bfloat162float(__low2bfloat16(h01)),
            v1 - __bfloat162float(__high2bfloat16(h01)));
        __nv_bfloat162 L23 = __floats2bfloat162_rn(
            v2 - __bfloat162float(__low2bfloat16(h23)),
            v3 - __bfloat162float(__high2bfloat16(h23)));
        *(__nv_bfloat162*)(Ohi + a0) = h01;
        *(__nv_bfloat162*)(Olo + a0) = L01;
        *(__nv_bfloat162*)(Ohi + a1) = h23;
        *(__nv_bfloat162*)(Olo + a1) = L23;
    }
}

// ---------------- embedding lookup ----------------
__global__ void embed_kernel(const int* __restrict__ tokens,
                             const float* __restrict__ emb,
                             float* __restrict__ x) {
    int row = blockIdx.x;
    int tok = tokens[row];
    const float4* src = (const float4*)(emb + (size_t)tok * DD);
    float4* dst = (float4*)(x + (size_t)row * DD);
    for (int i = threadIdx.x; i < DD/4; i += blockDim.x) dst[i] = src[i];
}

// ---------------- layernorm -> bf16 hi/lo planes ----------------
__global__ void ln_kernel(const float* __restrict__ x,
                          const float* __restrict__ gw,
                          const float* __restrict__ bw,
                          __nv_bfloat16* __restrict__ hi,
                          __nv_bfloat16* __restrict__ lo) {
    int row = blockIdx.x;
    const float* xr = x + (size_t)row * DD;
    float s = 0.f, s2 = 0.f;
    for (int i = threadIdx.x; i < DD; i += 256) {
        float v = xr[i];
        s += v;
        s2 = fmaf(v, v, s2);
    }
    __shared__ float rs[8], rs2[8];
    #pragma unroll
    for (int o = 16; o > 0; o >>= 1) {
        s  += __shfl_down_sync(0xffffffffu, s,  o);
        s2 += __shfl_down_sync(0xffffffffu, s2, o);
    }
    int w = threadIdx.x >> 5;
    if ((threadIdx.x & 31) == 0) { rs[w] = s; rs2[w] = s2; }
    __syncthreads();
    __shared__ float mean_s, rstd_s;
    if (threadIdx.x == 0) {
        float ts = 0.f, ts2 = 0.f;
        #pragma unroll
        for (int i = 0; i < 8; i++) { ts += rs[i]; ts2 += rs2[i]; }
        float m = ts / (float)DD;
        float var = ts2 / (float)DD - m * m;
        mean_s = m;
        rstd_s = rsqrtf(var + 1e-5f);
    }
    __syncthreads();
    float m = mean_s, r = rstd_s;
    __nv_bfloat16* hrow = hi + (size_t)row * DD;
    __nv_bfloat16* lrow = lo + (size_t)row * DD;
    for (int i = threadIdx.x; i < DD; i += 256) {
        float v = (xr[i] - m) * r * gw[i] + bw[i];
        __nv_bfloat16 vh, vl;
        split1(v, vh, vl);
        hrow[i] = vh;
        lrow[i] = vl;
    }
}

// ---------------- SwiGLU combine -> bf16 hi/lo ----------------
__global__ void swiglu_kernel(const float* __restrict__ a, const float* __restrict__ c,
                              __nv_bfloat16* __restrict__ hi,
                              __nv_bfloat16* __restrict__ lo) {
    int i = blockIdx.x * 256 + threadIdx.x;
    float4 x4 = ((const float4*)a)[i];
    float4 c4 = ((const float4*)c)[i];
    float r0 = x4.x / (1.f + __expf(-x4.x)) * c4.x;
    float r1 = x4.y / (1.f + __expf(-x4.y)) * c4.y;
    float r2 = x4.z / (1.f + __expf(-x4.z)) * c4.z;
    float r3 = x4.w / (1.f + __expf(-x4.w)) * c4.w;
    __nv_bfloat16 h0,h1,h2,h3,l0,l1,l2,l3;
    split1(r0, h0, l0); split1(r1, h1, l1);
    split1(r2, h2, l2); split1(r3, h3, l3);
    ((ushort4*)hi)[i] = make_ushort4(__bfloat16_as_ushort(h0), __bfloat16_as_ushort(h1),
                                     __bfloat16_as_ushort(h2), __bfloat16_as_ushort(h3));
    ((ushort4*)lo)[i] = make_ushort4(__bfloat16_as_ushort(l0), __bfloat16_as_ushort(l1),
                                     __bfloat16_as_ushort(l2), __bfloat16_as_ushort(l3));
}

// ---------------- launch ----------------
extern "C" void kernel_launch(void* const* d_in, const int* in_sizes, int n_in,
                              void* d_out, int out_size) {
    const int*   tokens = (const int*)d_in[0];
    const float* emb    = (const float*)d_in[1];
    const float* wq     = (const float*)d_in[2];
    const float* wk     = (const float*)d_in[3];
    const float* wv     = (const float*)d_in[4];
    const float* wo     = (const float*)d_in[5];
    const float* ln1_g  = (const float*)d_in[6];
    const float* ln1_b  = (const float*)d_in[7];
    const float* ln2_g  = (const float*)d_in[8];
    const float* ln2_b  = (const float*)d_in[9];
    const float* w1     = (const float*)d_in[10];
    const float* w2     = (const float*)d_in[11];
    const float* w3     = (const float*)d_in[12];
    const float* lnf_g  = (const float*)d_in[13];
    const float* lnf_b  = (const float*)d_in[14];
    const float* w_out  = (const float*)d_in[15];
    float* out = (float*)d_out;

    float *px, *pq, *pk, *pv;
    cudaGetSymbolAddress((void**)&px, g_x);
    cudaGetSymbolAddress((void**)&pq, g_q);
    cudaGetSymbolAddress((void**)&pk, g_k);
    cudaGetSymbolAddress((void**)&pv, g_v);
    __nv_bfloat16 *whi, *wlo, *ahi, *alo;
    cudaGetSymbolAddress((void**)&whi, g_whi);
    cudaGetSymbolAddress((void**)&wlo, g_wlo);
    cudaGetSymbolAddress((void**)&ahi, g_ahi);
    cudaGetSymbolAddress((void**)&alo, g_alo);

    cudaFuncSetAttribute(attn_mma,
                         cudaFuncAttributeMaxDynamicSharedMemorySize, ASMEM);
    cudaFuncSetAttribute(gemm_mma<false>,
                         cudaFuncAttributeMaxDynamicSharedMemorySize, GSMEM);
    cudaFuncSetAttribute(gemm_mma<true>,
                         cudaFuncAttributeMaxDynamicSharedMemorySize, GSMEM);

    // ---- convert all weights to bf16 hi/lo planes ----
    {
        int n4w = (LL * WMAT) / 4;
        conv_split<<<n4w/256, 256>>>(wq, whi + WQ_OFF, wlo + WQ_OFF, n4w);
        conv_split<<<n4w/256, 256>>>(wk, whi + WK_OFF, wlo + WK_OFF, n4w);
        conv_split<<<n4w/256, 256>>>(wv, whi + WV_OFF, wlo + WV_OFF, n4w);
        conv_split<<<n4w/256, 256>>>(wo, whi + WO_OFF, wlo + WO_OFF, n4w);
        conv_split<<<n4w/256, 256>>>(w1, whi + W1_OFF, wlo + W1_OFF, n4w);
        conv_split<<<n4w/256, 256>>>(w2, whi + W2_OFF, wlo + W2_OFF, n4w);
        conv_split<<<n4w/256, 256>>>(w3, whi + W3_OFF, wlo + W3_OFF, n4w);
        int n4o = (VV * DD) / 4;
        conv_split<<<n4o/256, 256>>>(w_out, whi + WOUT_OFF, wlo + WOUT_OFF, n4o);
    }

    embed_kernel<<<MM, 256>>>(tokens, emb, px);

    dim3 gg(DD/128, MM/128);
    for (int l = 0; l < LL; l++) {
        size_t lo_off = (size_t)l * WMAT;

        // attention
        ln_kernel<<<MM, 256>>>(px, ln1_g + l*DD, ln1_b + l*DD, ahi, alo);
        gemm_mma<false><<<gg, 256, GSMEM>>>(ahi, alo, whi + WQ_OFF + lo_off,
                                            wlo + WQ_OFF + lo_off, nullptr, pq, DD, DD);
        gemm_mma<false><<<gg, 256, GSMEM>>>(ahi, alo, whi + WK_OFF + lo_off,
                                            wlo + WK_OFF + lo_off, nullptr, pk, DD, DD);
        gemm_mma<false><<<gg, 256, GSMEM>>>(ahi, alo, whi + WV_OFF + lo_off,
                                            wlo + WV_OFF + lo_off, nullptr, pv, DD, DD);
        attn_mma<<<dim3(SS/64, BB*HH), 128, ASMEM>>>(pq, pk, pv, ahi, alo);
        gemm_mma<true><<<gg, 256, GSMEM>>>(ahi, alo, whi + WO_OFF + lo_off,
                                           wlo + WO_OFF + lo_off, px, px, DD, DD);

        // SwiGLU FFN
        ln_kernel<<<MM, 256>>>(px, ln2_g + l*DD, ln2_b + l*DD, ahi, alo);
        gemm_mma<false><<<gg, 256, GSMEM>>>(ahi, alo, whi + W1_OFF + lo_off,
                                            wlo + W1_OFF + lo_off, nullptr, pq, DD, DD);
        gemm_mma<false><<<gg, 256, GSMEM>>>(ahi, alo, whi + W3_OFF + lo_off,
                                            wlo + W3_OFF + lo_off, nullptr, pk, DD, DD);
        swiglu_kernel<<<(MM*DD/4)/256, 256>>>(pq, pk, ahi, alo);
        gemm_mma<true><<<gg, 256, GSMEM>>>(ahi, alo, whi + W2_OFF + lo_off,
                                           wlo + W2_OFF + lo_off, px, px, DD, DD);
    }

    // final LN + logits
    ln_kernel<<<MM, 256>>>(px, lnf_g, lnf_b, ahi, alo);
    gemm_mma<false><<<dim3(VV/128, MM/128), 256, GSMEM>>>(
        ahi, alo, whi + WOUT_OFF, wlo + WOUT_OFF, nullptr, out, VV, DD);
}